// round 14
// baseline (speedup 1.0000x reference)
#include <cuda_runtime.h>
#include <cuda_bf16.h>
#include <cstdint>

// Fixed shapes for HRTExtractor_81320910782627
#define N_DOCS 4
#define LSEQ   1024
#define DMODEL 768
#define NHEAD  12
#define NE     32
#define NM     4
#define NR     256
#define POS_OFFSET 1
#define NEG_INF (-3.402823466e38f)

#define LC   32
#define NLC  (LSEQ / LC)      // 32

// Scratch (device globals; allocation forbidden)
__device__ float    g_eemb[N_DOCS * NE * DMODEL];          // (i,e,d)
__device__ float    g_eatt[N_DOCS * NE * NHEAD * LSEQ];    // (i,e,h,l)
__device__ float    g_v   [N_DOCS * NR * LSEQ];            // unnormalized ht_att
__device__ float    g_spart[N_DOCS * NR * NLC];            // per-chunk partial sums
__device__ unsigned g_htp_hi[N_DOCS * NR * (LSEQ / 2)];    // packed bf16x2 hi
__device__ unsigned g_htp_lo[N_DOCS * NR * (LSEQ / 2)];    // packed bf16x2 lo

// ---------------------------------------------------------------------------
__device__ __forceinline__ void bsplit(float x, float& hi, float& lo) {
    __nv_bfloat16 h = __float2bfloat16(x);
    float hf = __bfloat162float(h);
    hi = hf;
    lo = x - hf;
}
__device__ __forceinline__ unsigned pack2(float a, float b) {
    __nv_bfloat162 v = __floats2bfloat162_rn(a, b);
    return *reinterpret_cast<unsigned*>(&v);
}

// ---------------------------------------------------------------------------
// Kernel 1 (fused): blocks [0, 4*32*6) -> e_att (2 heads/block),
//                   blocks [.., +128)  -> e_emb (logsumexp)   [unchanged]
// ---------------------------------------------------------------------------
#define NHP (NHEAD / 2)   // 6 head-pairs

__global__ __launch_bounds__(256) void k_prep(
    const float* __restrict__ seq,      // (n, L, d)
    const float* __restrict__ att,      // (n, h, L, L)
    const int*   __restrict__ mpos,     // (n, E, M)
    const float* __restrict__ mmask)    // (n, E, M)
{
    if (blockIdx.x < N_DOCS * NE * NHP) {
        int b  = blockIdx.x;
        int hp = b % NHP;
        int ie = b / NHP;
        int i  = ie / NE;
        int h0 = hp * 2;

        int   p[NM];
        float mk[NM];
        float cnt = 0.f;
        #pragma unroll
        for (int m = 0; m < NM; m++) {
            p[m]  = mpos[ie * NM + m] + POS_OFFSET;
            mk[m] = mmask[ie * NM + m];
            cnt += mk[m];
        }
        float inv = 1.f / fmaxf(cnt, 1.f);

        int l4 = threadIdx.x * 4;
        float4 a0 = make_float4(0.f, 0.f, 0.f, 0.f);
        float4 a1 = make_float4(0.f, 0.f, 0.f, 0.f);
        #pragma unroll
        for (int m = 0; m < NM; m++) {
            const float4 x = *(const float4*)&att[
                (((size_t)i * NHEAD + h0)     * LSEQ + p[m]) * LSEQ + l4];
            const float4 y = *(const float4*)&att[
                (((size_t)i * NHEAD + h0 + 1) * LSEQ + p[m]) * LSEQ + l4];
            a0.x += mk[m] * x.x; a0.y += mk[m] * x.y;
            a0.z += mk[m] * x.z; a0.w += mk[m] * x.w;
            a1.x += mk[m] * y.x; a1.y += mk[m] * y.y;
            a1.z += mk[m] * y.z; a1.w += mk[m] * y.w;
        }
        float4 o0 = make_float4(a0.x * inv, a0.y * inv, a0.z * inv, a0.w * inv);
        float4 o1 = make_float4(a1.x * inv, a1.y * inv, a1.z * inv, a1.w * inv);
        *(float4*)&g_eatt[((size_t)ie * NHEAD + h0)     * LSEQ + l4] = o0;
        *(float4*)&g_eatt[((size_t)ie * NHEAD + h0 + 1) * LSEQ + l4] = o1;
    } else {
        int ie = blockIdx.x - N_DOCS * NE * NHP;
        int i  = ie / NE;

        __shared__ int   sp[NM];
        __shared__ float sm[NM];
        if (threadIdx.x < NM) {
            sp[threadIdx.x] = mpos[ie * NM + threadIdx.x] + POS_OFFSET;
            sm[threadIdx.x] = mmask[ie * NM + threadIdx.x];
        }
        __syncthreads();

        for (int dd = threadIdx.x; dd < DMODEL; dd += blockDim.x) {
            float v[NM];
            float mx = NEG_INF;
            #pragma unroll
            for (int m = 0; m < NM; m++) {
                float x = (sm[m] > 0.f)
                    ? seq[((size_t)i * LSEQ + sp[m]) * DMODEL + dd]
                    : NEG_INF;
                v[m] = x;
                mx = fmaxf(mx, x);
            }
            float s = 0.f;
            #pragma unroll
            for (int m = 0; m < NM; m++) s += expf(v[m] - mx);
            g_eemb[(size_t)ie * DMODEL + dd] = logf(s) + mx;
        }
    }
}

// ---------------------------------------------------------------------------
// Kernel 2: k_htA — smem-tiled pairwise head dot (unchanged, proven).
// ---------------------------------------------------------------------------
__global__ __launch_bounds__(256) void k_htA(const int* __restrict__ hts)
{
    __shared__ __align__(16) float sA[NHEAD][NE][LC];   // 48 KB

    const int lc = blockIdx.x;
    const int i  = blockIdx.y;
    const int rh = blockIdx.z;
    const int l0 = lc * LC;

    for (int idx = threadIdx.x; idx < NHEAD * NE * (LC / 4); idx += 256) {
        int q  = idx & (LC / 4 - 1);
        int eh = idx >> 3;
        int e  = eh & (NE - 1);
        int h  = eh >> 5;
        float4 v = *(const float4*)&g_eatt[
            ((size_t)(i * NE + e) * NHEAD + h) * LSEQ + l0 + q * 4];
        *(float4*)&sA[h][e][q * 4] = v;
    }
    __syncthreads();

    const int warp = threadIdx.x >> 5;
    const int lane = threadIdx.x & 31;
    const int rbase = rh * 128 + warp * 16;

    int2 ep = ((const int2*)hts)[i * NR + rbase + (lane & 15)];
    float* vout = g_v + ((size_t)i * NR + rbase) * LSEQ + l0;

    #pragma unroll 4
    for (int rr = 0; rr < 16; rr++) {
        int e0 = __shfl_sync(0xffffffffu, ep.x, rr);
        int e1 = __shfl_sync(0xffffffffu, ep.y, rr);
        float acc = 0.f;
        #pragma unroll
        for (int h = 0; h < NHEAD; h++)
            acc += sA[h][e0][lane] * sA[h][e1][lane];
        acc *= (1.f / NHEAD);
        vout[(size_t)rr * LSEQ + lane] = acc;

        float t = acc;
        #pragma unroll
        for (int o = 16; o; o >>= 1) t += __shfl_xor_sync(0xffffffffu, t, o);
        if (lane == 0)
            g_spart[(size_t)(i * NR + rbase + rr) * NLC + lc] = t;
    }
}

// ---------------------------------------------------------------------------
// Kernel 3: k_pack — normalize + bf16 split/pack + hs/ts copy (unchanged).
// ---------------------------------------------------------------------------
__global__ __launch_bounds__(256) void k_pack(
    const int* __restrict__ hts,
    float* __restrict__ out)
{
    const int b = blockIdx.x;           // i*NR + r
    const int i = b / NR;

    __shared__ float s_scl;
    if (threadIdx.x < 32) {
        float v = g_spart[(size_t)b * NLC + threadIdx.x];
        #pragma unroll
        for (int o = 16; o; o >>= 1) v += __shfl_xor_sync(0xffffffffu, v, o);
        if (threadIdx.x == 0) s_scl = 1.f / (v + 1e-5f);
    }
    __syncthreads();
    const float scl = s_scl;

    {
        float4 v = ((const float4*)(g_v + (size_t)b * LSEQ))[threadIdx.x];
        float f0 = v.x * scl, f1 = v.y * scl, f2 = v.z * scl, f3 = v.w * scl;
        float h0, l0, h1, l1, h2, l2, h3, l3;
        bsplit(f0, h0, l0); bsplit(f1, h1, l1);
        bsplit(f2, h2, l2); bsplit(f3, h3, l3);
        uint2 phi = make_uint2(pack2(h0, h1), pack2(h2, h3));
        uint2 plo = make_uint2(pack2(l0, l1), pack2(l2, l3));
        *(uint2*)&g_htp_hi[(size_t)b * (LSEQ / 2) + threadIdx.x * 2] = phi;
        *(uint2*)&g_htp_lo[(size_t)b * (LSEQ / 2) + threadIdx.x * 2] = plo;
    }

    {
        int e0 = hts[b * 2 + 0];
        int e1 = hts[b * 2 + 1];
        const float4* eh = (const float4*)&g_eemb[(size_t)(i * NE + e0) * DMODEL];
        const float4* et = (const float4*)&g_eemb[(size_t)(i * NE + e1) * DMODEL];
        float4* o0 = (float4*)&out[(size_t)b * DMODEL];
        float4* o1 = (float4*)&out[((size_t)N_DOCS * NR + b) * DMODEL];
        if (threadIdx.x < 192) {
            o0[threadIdx.x] = eh[threadIdx.x];
            o1[threadIdx.x] = et[threadIdx.x];
        }
    }
}

// ---------------------------------------------------------------------------
// Kernel 4: rs = ht @ seq via HMMA bf16 3-term split. REDESIGNED:
//  - BM=64, BN=64, BK=16 -> grid (12,4,4)=192 blocks (full 148-SM coverage,
//    2 CTAs co-resident on 44 SMs).
//  - Double-buffered smem (24 KB static), ONE barrier per iteration;
//    LDG issued 2 tiles ahead.
//  - Smem row stride 12 u32: LDSM conflict-free ({12r mod 32} covers all
//    banks); ldmatrix lane mapping identical to proven r13 formulas.
//  - 8 warps, warp tile 32x16 (warps 2m x 4n).
// ---------------------------------------------------------------------------
#define GBM 64
#define GBN 64
#define GBK 16
#define ASTR 12                     // u32 per row (8 data + 4 pad)
#define ABUF (GBM * ASTR)           // 768 u32 per buffer
#define BBUF (GBN * ASTR)           // 768 u32 per buffer
#define NTILE (LSEQ / GBK)          // 64 iterations

__device__ __forceinline__ void mma16816(
    float& c0, float& c1, float& c2, float& c3,
    unsigned a0, unsigned a1, unsigned a2, unsigned a3,
    unsigned b0, unsigned b1)
{
    asm volatile(
        "mma.sync.aligned.m16n8k16.row.col.f32.bf16.bf16.f32 "
        "{%0,%1,%2,%3}, {%4,%5,%6,%7}, {%8,%9}, {%0,%1,%2,%3};\n"
        : "+f"(c0), "+f"(c1), "+f"(c2), "+f"(c3)
        : "r"(a0), "r"(a1), "r"(a2), "r"(a3), "r"(b0), "r"(b1));
}

__device__ __forceinline__ void ldsm4(
    unsigned& r0, unsigned& r1, unsigned& r2, unsigned& r3, unsigned addr)
{
    asm volatile(
        "ldmatrix.sync.aligned.m8n8.x4.shared.b16 {%0,%1,%2,%3}, [%4];\n"
        : "=r"(r0), "=r"(r1), "=r"(r2), "=r"(r3) : "r"(addr));
}

__global__ __launch_bounds__(256) void k_gemm(
    const float* __restrict__ seq,      // (n, L, d)
    float* __restrict__ out)
{
    __shared__ __align__(16) unsigned As_hi[2][ABUF];
    __shared__ __align__(16) unsigned As_lo[2][ABUF];
    __shared__ __align__(16) unsigned Bs_hi[2][BBUF];
    __shared__ __align__(16) unsigned Bs_lo[2][BBUF];

    const int i       = blockIdx.z;
    const int rowBase = blockIdx.y * GBM;
    const int colBase = blockIdx.x * GBN;

    const int tid  = threadIdx.x;
    const int wid  = tid >> 5;
    const int lane = tid & 31;
    const int g    = lane >> 2;
    const int q    = lane & 3;

    const int warp_m = (wid & 1) * 32;   // 0,32
    const int warp_n = (wid >> 1) * 16;  // 0,16,32,48

    // ---- copy assignments ----
    // A: thread t<128 loads hi, t>=128 loads lo. c = t&127: row=c>>1, off=(c&1)*4
    const int ahalf = tid >> 7;
    const int ac    = tid & 127;
    const int arow  = ac >> 1;
    const int aoff  = (ac & 1) * 4;
    const unsigned* Asrc =
        (ahalf ? g_htp_lo : g_htp_hi)
        + (size_t)(i * NR + rowBase + arow) * (LSEQ / 2) + aoff;
    // B: n = t&63, kq = t>>6 (0..3); handles k2 = kq and kq+4
    const int bn = tid & 63;
    const int bkq = tid >> 6;
    const float* Bsrc = seq + (size_t)i * LSEQ * DMODEL + colBase + bn;

    // ---- ldmatrix lane addresses (r13-proven mapping; stride 12) ----
    const int a_row = lane & 15;
    const int a_kp  = (lane >> 4) * 4;
    const int b_row = (lane & 7) | ((lane >> 1) & 8);
    const int b_kp  = ((lane >> 3) & 1) * 4;

    unsigned baseAh = (unsigned)__cvta_generic_to_shared(&As_hi[0][0]);
    unsigned baseAl = (unsigned)__cvta_generic_to_shared(&As_lo[0][0]);
    unsigned baseBh = (unsigned)__cvta_generic_to_shared(&Bs_hi[0][0]);
    unsigned baseBl = (unsigned)__cvta_generic_to_shared(&Bs_lo[0][0]);

    unsigned offA[2];
    #pragma unroll
    for (int mt = 0; mt < 2; mt++)
        offA[mt] = ((warp_m + mt * 16 + a_row) * ASTR + a_kp) * 4u;
    const unsigned offB = ((warp_n + b_row) * ASTR + b_kp) * 4u;

    float c[2][2][4];
    #pragma unroll
    for (int mt = 0; mt < 2; mt++)
        #pragma unroll
        for (int nt = 0; nt < 2; nt++)
            #pragma unroll
            for (int r = 0; r < 4; r++) c[mt][nt][r] = 0.f;

    uint4 rA;
    float rB[4];

    // tile loader: tile index tt -> regs
    auto loadTile = [&](int tt) {
        rA = *(const uint4*)&Asrc[tt * 8];
        int k0 = tt * GBK + 2 * bkq;
        rB[0] = Bsrc[(size_t)(k0)     * DMODEL];
        rB[1] = Bsrc[(size_t)(k0 + 1) * DMODEL];
        rB[2] = Bsrc[(size_t)(k0 + 8) * DMODEL];
        rB[3] = Bsrc[(size_t)(k0 + 9) * DMODEL];
    };
    // reg -> smem buffer nb
    auto storeTile = [&](int nb) {
        if (ahalf == 0)
            *(uint4*)&As_hi[nb][arow * ASTR + aoff] = rA;
        else
            *(uint4*)&As_lo[nb][arow * ASTR + aoff] = rA;
        float h0, l0, h1, l1, h2, l2, h3, l3;
        bsplit(rB[0], h0, l0); bsplit(rB[1], h1, l1);
        bsplit(rB[2], h2, l2); bsplit(rB[3], h3, l3);
        Bs_hi[nb][bn * ASTR + bkq]     = pack2(h0, h1);
        Bs_hi[nb][bn * ASTR + bkq + 4] = pack2(h2, h3);
        Bs_lo[nb][bn * ASTR + bkq]     = pack2(l0, l1);
        Bs_lo[nb][bn * ASTR + bkq + 4] = pack2(l2, l3);
    };

    // ---- prologue ----
    loadTile(0);
    storeTile(0);
    loadTile(1);
    __syncthreads();

    for (int it = 0; it < NTILE; it++) {
        const int cur = it & 1;
        if (it + 1 < NTILE) storeTile(cur ^ 1);   // regs hold tile it+1
        if (it + 2 < NTILE) loadTile(it + 2);

        const unsigned selA = cur * (ABUF * 4u);
        const unsigned selB = cur * (BBUF * 4u);

        unsigned ah[2][4], al[2][4];
        #pragma unroll
        for (int mt = 0; mt < 2; mt++) {
            ldsm4(ah[mt][0], ah[mt][1], ah[mt][2], ah[mt][3],
                  baseAh + selA + offA[mt]);
            ldsm4(al[mt][0], al[mt][1], al[mt][2], al[mt][3],
                  baseAl + selA + offA[mt]);
        }
        unsigned bh[2][2], bl[2][2];
        ldsm4(bh[0][0], bh[0][1], bh[1][0], bh[1][1], baseBh + selB + offB);
        ldsm4(bl[0][0], bl[0][1], bl[1][0], bl[1][1], baseBl + selB + offB);

        #pragma unroll
        for (int mt = 0; mt < 2; mt++)
            #pragma unroll
            for (int nt = 0; nt < 2; nt++) {
                float* cc = c[mt][nt];
                mma16816(cc[0], cc[1], cc[2], cc[3],
                         ah[mt][0], ah[mt][1], ah[mt][2], ah[mt][3],
                         bh[nt][0], bh[nt][1]);
                mma16816(cc[0], cc[1], cc[2], cc[3],
                         ah[mt][0], ah[mt][1], ah[mt][2], ah[mt][3],
                         bl[nt][0], bl[nt][1]);
                mma16816(cc[0], cc[1], cc[2], cc[3],
                         al[mt][0], al[mt][1], al[mt][2], al[mt][3],
                         bh[nt][0], bh[nt][1]);
            }
        __syncthreads();
    }

    // ---- epilogue: rs block ----
    float* O = out + ((size_t)2 * N_DOCS * NR + (size_t)i * NR) * DMODEL;
    #pragma unroll
    for (int mt = 0; mt < 2; mt++) {
        int row0 = rowBase + warp_m + mt * 16 + g;
        #pragma unroll
        for (int nt = 0; nt < 2; nt++) {
            int col = colBase + warp_n + nt * 8 + 2 * q;
            float2 v0 = make_float2(c[mt][nt][0], c[mt][nt][1]);
            float2 v1 = make_float2(c[mt][nt][2], c[mt][nt][3]);
            *(float2*)&O[(size_t)row0 * DMODEL + col]       = v0;
            *(float2*)&O[(size_t)(row0 + 8) * DMODEL + col] = v1;
        }
    }
}

// ---------------------------------------------------------------------------
extern "C" void kernel_launch(void* const* d_in, const int* in_sizes, int n_in,
                              void* d_out, int out_size)
{
    const float* seq   = (const float*)d_in[0];   // (4,1024,768) f32
    const float* att   = (const float*)d_in[1];   // (4,12,1024,1024) f32
    const int*   mpos  = (const int*)  d_in[2];   // (4,32,4) i32
    const float* mmask = (const float*)d_in[3];   // (4,32,4) f32
    const int*   hts   = (const int*)  d_in[4];   // (4,256,2) i32
    float* out = (float*)d_out;                   // (3, 4*256, 768) f32

    k_prep<<<N_DOCS * NE * NHP + N_DOCS * NE, 256>>>(seq, att, mpos, mmask);
    k_htA <<<dim3(NLC, N_DOCS, 2), 256>>>(hts);
    k_pack<<<N_DOCS * NR, 256>>>(hts, out);
    k_gemm<<<dim3(DMODEL / GBN, NR / GBM, N_DOCS), 256>>>(seq, out);
}